// round 1
// baseline (speedup 1.0000x reference)
#include <cuda_runtime.h>
#include <math.h>

// Problem constants (B=4, S=2048, D_IN=1024, D_OUT=1024, E=8, K=2)
#define BTOK   8192      // B*S tokens
#define DIN    1024
#define DOUT   1024
#define NE     8
#define NROW   24        // 8 gate rows + 16 expert rows (e, o in {0,1})
#define TM     64        // tokens per block
#define TK     128       // K chunk
#define THREADS 256

#define XS_STRIDE 132    // 128 + 4 pad (float4-aligned, de-conflicted)
#define WS_STRIDE 129    // bank = (row + kk) % 32 -> conflict-free w reads

__global__ __launch_bounds__(THREADS)
void moe_fused_kernel(const float* __restrict__ x,
                      const float* __restrict__ gate_w,
                      const float* __restrict__ gate_b,
                      const float* __restrict__ ebias,
                      const float* __restrict__ expert_w,
                      const float* __restrict__ expert_b,
                      float* __restrict__ out,
                      float* __restrict__ idx_out)
{
    __shared__ float xs[TM][XS_STRIDE];              // 33792 B
    __shared__ float ws[NROW][WS_STRIDE];            // 12384 B
    __shared__ float wtok[TM];
    __shared__ const float* rowsrc[NROW];

    const int tid  = threadIdx.x;
    const int tok0 = blockIdx.x * TM;

    // thread tile: og in [0,8) -> 3 outputs; tg in [0,32) -> 2 tokens
    const int og = tid & 7;
    const int tg = tid >> 3;

    if (tid < NROW) {
        rowsrc[tid] = (tid < NE)
            ? (gate_w + (size_t)tid * DIN)
            : (expert_w + ((size_t)(((tid - NE) >> 1) * DOUT + ((tid - NE) & 1))) * DIN);
    }

    float acc[2][3];
    #pragma unroll
    for (int t = 0; t < 2; t++)
        #pragma unroll
        for (int n = 0; n < 3; n++) acc[t][n] = 0.f;

    for (int k0 = 0; k0 < DIN; k0 += TK) {
        __syncthreads();   // previous compute done (and rowsrc visible on first iter)

        // ---- load x chunk: warp-coherent rows, float4 coalesced ----
        #pragma unroll
        for (int r = 0; r < (TM * TK) / (4 * THREADS); r++) {   // 8 iters
            int t  = tid + r * THREADS;
            int m  = t >> 5;            // token row (constant per warp)
            int f4 = (t & 31) << 2;     // float offset within 128-float row
            float4 v = *(const float4*)(x + (size_t)(tok0 + m) * DIN + k0 + f4);
            *(float4*)&xs[m][f4] = v;
        }

        // ---- load weight chunk (24 rows x 128) ----
        #pragma unroll
        for (int r = 0; r < (NROW * TK) / THREADS; r++) {       // 12 iters
            int t   = tid + r * THREADS;
            int row = t >> 7;           // TK = 128
            int kk  = t & 127;
            ws[row][kk] = rowsrc[row][k0 + kk];
        }

        __syncthreads();

        // ---- inner product: 2 tokens x 3 outputs per thread ----
        const float* xr0 = &xs[tg * 2 + 0][0];
        const float* xr1 = &xs[tg * 2 + 1][0];
        const float* wr0 = &ws[og * 3 + 0][0];
        const float* wr1 = &ws[og * 3 + 1][0];
        const float* wr2 = &ws[og * 3 + 2][0];
        #pragma unroll 32
        for (int kk = 0; kk < TK; kk++) {
            float x0 = xr0[kk];
            float x1 = xr1[kk];
            float w0 = wr0[kk];
            float w1 = wr1[kk];
            float w2 = wr2[kk];
            acc[0][0] = fmaf(x0, w0, acc[0][0]);
            acc[0][1] = fmaf(x0, w1, acc[0][1]);
            acc[0][2] = fmaf(x0, w2, acc[0][2]);
            acc[1][0] = fmaf(x1, w0, acc[1][0]);
            acc[1][1] = fmaf(x1, w1, acc[1][1]);
            acc[1][2] = fmaf(x1, w2, acc[1][2]);
        }
    }

    // ---- stash P[64][24] (overlay onto xs; all xs reads are done after sync) ----
    __syncthreads();
    float* Pbuf = &xs[0][0];            // stride 25 floats per token
    #pragma unroll
    for (int t = 0; t < 2; t++)
        #pragma unroll
        for (int n = 0; n < 3; n++)
            Pbuf[(tg * 2 + t) * 25 + (og * 3 + n)] = acc[t][n];
    __syncthreads();

    // ---- per-token top-2 + sigmoid + combine (threads 0..63) ----
    if (tid < TM) {
        const float* Pm = Pbuf + tid * 25;
        float l[NE];
        #pragma unroll
        for (int e = 0; e < NE; e++)
            l[e] = Pm[e] + gate_b[e] + ebias[e];

        // argmax with first-occurrence tie-break (matches lax.top_k)
        int e0 = 0; float b0 = l[0];
        #pragma unroll
        for (int e = 1; e < NE; e++)
            if (l[e] > b0) { b0 = l[e]; e0 = e; }
        int e1 = -1; float b1 = -INFINITY;
        #pragma unroll
        for (int e = 0; e < NE; e++) {
            if (e == e0) continue;
            if (l[e] > b1) { b1 = l[e]; e1 = e; }
        }

        float p0 = 1.f / (1.f + expf(-b0));
        float p1 = 1.f / (1.f + expf(-b1));
        float inv = 1.f / (p0 + p1);

        float v0 = Pm[NE + e0 * 2 + 0] + expert_b[(size_t)e0 * DOUT + 0];
        float v1 = Pm[NE + e1 * 2 + 1] + expert_b[(size_t)e1 * DOUT + 1];
        wtok[tid] = (v0 * p0 + v1 * p1) * inv;

        if (idx_out) {
            idx_out[(size_t)(tok0 + tid) * 2 + 0] = (float)e0;
            idx_out[(size_t)(tok0 + tid) * 2 + 1] = (float)e1;
        }
    }
    __syncthreads();

    // ---- broadcast write: token m -> 1024 identical floats (float4 coalesced) ----
    const int fo = tid << 2;            // 256 threads * 4 floats = 1024
    #pragma unroll 4
    for (int m = 0; m < TM; m++) {
        float v = wtok[m];
        float4 v4 = make_float4(v, v, v, v);
        *(float4*)(out + (size_t)(tok0 + m) * DOUT + fo) = v4;
    }
}

extern "C" void kernel_launch(void* const* d_in, const int* in_sizes, int n_in,
                              void* d_out, int out_size)
{
    const float* x        = (const float*)d_in[0];
    const float* gate_w   = (const float*)d_in[1];
    const float* gate_b   = (const float*)d_in[2];
    const float* ebias    = (const float*)d_in[3];
    const float* expert_w = (const float*)d_in[4];
    const float* expert_b = (const float*)d_in[5];
    float* out = (float*)d_out;

    // If d_out holds both outputs concatenated (final_output then top_k_indices),
    // write the indices (cast to float) into the tail.
    float* idx_out = nullptr;
    long long base = (long long)BTOK * DOUT;
    if ((long long)out_size >= base + (long long)BTOK * 2)
        idx_out = out + base;

    moe_fused_kernel<<<BTOK / TM, THREADS>>>(x, gate_w, gate_b, ebias,
                                             expert_w, expert_b, out, idx_out);
}